// round 1
// baseline (speedup 1.0000x reference)
#include <cuda_runtime.h>
#include <cstdint>

#define Bsz 8
#define Nn 2048
#define Fd 256

// scratch (device globals; no allocation allowed)
__device__ float g_Wh[Bsz * Nn * Fd];          // 64 MB
__device__ float g_E1p[Bsz * Nn];
__device__ float g_E1n[Bsz * Nn];
__device__ float g_E2p[Bsz * Nn];
__device__ float g_E2n[Bsz * Nn];

// packed fp32x2 FMA (Blackwell FFMA2)
#define FFMA2(d, a, b, c) \
    asm("fma.rn.f32x2 %0, %1, %2, %3;" : "=l"(d) : "l"(a), "l"(b), "l"(c))
#define PACK2(out, x) \
    asm("mov.b64 %0, {%1, %1};" : "=l"(out) : "r"(x))

// ---------------------------------------------------------------------------
// K1: Wh = h @ W   (16384 x 256 x 256 GEMM, fp32)
// ---------------------------------------------------------------------------
__global__ __launch_bounds__(256) void gemm1_kernel(const float* __restrict__ h,
                                                    const float* __restrict__ W) {
    __shared__ float As[16][68];   // transposed A tile [k][i]
    __shared__ float Bs[16][64];   // [k][f]
    int tid = threadIdx.x;
    int i0 = blockIdx.x * 64;
    int f0 = blockIdx.y * 64;
    int tx = tid & 15;        // f subtile
    int ty = tid >> 4;        // i subtile
    float acc[4][4] = {};
    for (int k0 = 0; k0 < 256; k0 += 16) {
        {
            int r = tid >> 2, c4 = (tid & 3) * 4;
            float4 v = *(const float4*)&h[(size_t)(i0 + r) * 256 + k0 + c4];
            As[c4 + 0][r] = v.x; As[c4 + 1][r] = v.y;
            As[c4 + 2][r] = v.z; As[c4 + 3][r] = v.w;
        }
        {
            int r = tid >> 4, c4 = (tid & 15) * 4;
            *(float4*)&Bs[r][c4] = *(const float4*)&W[(size_t)(k0 + r) * 256 + f0 + c4];
        }
        __syncthreads();
#pragma unroll
        for (int k = 0; k < 16; k++) {
            float4 a = *(const float4*)&As[k][ty * 4];
            float4 b = *(const float4*)&Bs[k][tx * 4];
            float av[4] = {a.x, a.y, a.z, a.w};
            float bv[4] = {b.x, b.y, b.z, b.w};
#pragma unroll
            for (int ii = 0; ii < 4; ii++)
#pragma unroll
                for (int jj = 0; jj < 4; jj++)
                    acc[ii][jj] += av[ii] * bv[jj];
        }
        __syncthreads();
    }
#pragma unroll
    for (int ii = 0; ii < 4; ii++) {
        float4 v = make_float4(acc[ii][0], acc[ii][1], acc[ii][2], acc[ii][3]);
        *(float4*)&g_Wh[(size_t)(i0 + ty * 4 + ii) * 256 + f0 + tx * 4] = v;
    }
}

// ---------------------------------------------------------------------------
// K2: per-row scores s1,s2 and the 4 factored exponentials
// ---------------------------------------------------------------------------
__global__ __launch_bounds__(256) void score_kernel(const float* __restrict__ a) {
    int row = blockIdx.x * 8 + (threadIdx.x >> 5);   // one warp per row
    int lane = threadIdx.x & 31;
    const float* wh = &g_Wh[(size_t)row * 256];
    float s1 = 0.f, s2 = 0.f;
#pragma unroll
    for (int c = 0; c < 8; c++) {
        int f = c * 32 + lane;
        float v = wh[f];
        s1 += v * a[f];
        s2 += v * a[256 + f];
    }
#pragma unroll
    for (int o = 16; o; o >>= 1) {
        s1 += __shfl_xor_sync(0xffffffffu, s1, o);
        s2 += __shfl_xor_sync(0xffffffffu, s2, o);
    }
    if (lane == 0) {
        g_E1p[row] = expf(s1);
        g_E1n[row] = expf(0.2f * s1);
        g_E2p[row] = expf(s2);
        g_E2n[row] = expf(0.2f * s2);
    }
}

// ---------------------------------------------------------------------------
// K3: fused masked-softmax attention aggregate + LayerNorm + exact GELU
//     block: 64 rows (i) x 256 cols (f), loops over j in tiles of 32
// ---------------------------------------------------------------------------
__global__ __launch_bounds__(256, 2) void attn_kernel(const float* __restrict__ adj,
                                                      const float* __restrict__ gamma,
                                                      const float* __restrict__ beta,
                                                      float* __restrict__ out) {
    __shared__ float whs[32][256];   // Wh tile [j][f]  32KB
    __shared__ float ps[32][68];     // p tile transposed [j][i], padded
    __shared__ float zsum[64];
    __shared__ float e1p_s[64], e1n_s[64];

    int tid = threadIdx.x;
    int b = blockIdx.y;
    int i0 = blockIdx.x * 64;

    if (tid < 64) {
        e1p_s[tid] = g_E1p[b * Nn + i0 + tid];
        e1n_s[tid] = g_E1n[b * Nn + i0 + tid];
        zsum[tid] = 0.f;
    }

    int f_idx = tid & 31;     // thread covers f = f_idx*4..+3 and 128+f_idx*4..+3
    int i_idx = tid >> 5;     // thread covers rows i_idx*8 .. i_idx*8+7

    unsigned long long acc2[8][4];
#pragma unroll
    for (int di = 0; di < 8; di++)
#pragma unroll
        for (int k = 0; k < 4; k++) acc2[di][k] = 0ull;

    const float* whbase = &g_Wh[(size_t)b * Nn * Fd];
    const float* adjbase = &adj[(size_t)b * Nn * Nn + (size_t)i0 * Nn];
    const float* e2p = &g_E2p[b * Nn];
    const float* e2n = &g_E2n[b * Nn];

    int ii = tid >> 3;              // 0..31
    int jj4 = (tid & 7) * 4;        // 0..28

    for (int j0 = 0; j0 < Nn; j0 += 32) {
        __syncthreads();   // prior FFMA phase done; also covers init on iter 0

        // load Wh tile (32 x 256 floats, coalesced float4)
#pragma unroll
        for (int k = 0; k < 8; k++) {
            int idx = tid + k * 256;       // float4 index
            int r = idx >> 6;
            int c = idx & 63;
            *(float4*)&whs[r][c * 4] =
                *(const float4*)&whbase[(size_t)(j0 + r) * 256 + c * 4];
        }

        // compute unnormalized p tile (64 x 32), two row-halves per thread
        float e2pv[4], e2nv[4];
#pragma unroll
        for (int c = 0; c < 4; c++) {
            e2pv[c] = e2p[j0 + jj4 + c];
            e2nv[c] = e2n[j0 + jj4 + c];
        }
#pragma unroll
        for (int half = 0; half < 2; half++) {
            int iR = ii + half * 32;
            float4 av = *(const float4*)&adjbase[(size_t)iR * Nn + j0 + jj4];
            float adjv[4] = {av.x, av.y, av.z, av.w};
            float e1pv = e1p_s[iR], e1nv = e1n_s[iR];
            float zpart = 0.f;
            float pv[4];
#pragma unroll
            for (int c = 0; c < 4; c++) {
                float t = e1pv * e2pv[c];
                float v = (t > 1.f) ? t : e1nv * e2nv[c];
                float p = adjv[c] * v;
                pv[c] = p;
                zpart += p;
            }
            zpart += __shfl_xor_sync(0xffffffffu, zpart, 1);
            zpart += __shfl_xor_sync(0xffffffffu, zpart, 2);
            zpart += __shfl_xor_sync(0xffffffffu, zpart, 4);
#pragma unroll
            for (int c = 0; c < 4; c++) ps[jj4 + c][iR] = pv[c];
            if ((tid & 7) == 0) zsum[iR] += zpart;
        }
        __syncthreads();

        // accumulate: acc[i][f] += p[i][j] * Wh[j][f]   (packed f32x2)
#pragma unroll 8
        for (int jj = 0; jj < 32; jj++) {
            float4 pa = *(const float4*)&ps[jj][i_idx * 8];
            float4 pb = *(const float4*)&ps[jj][i_idx * 8 + 4];
            unsigned long long pp[8];
            PACK2(pp[0], __float_as_uint(pa.x));
            PACK2(pp[1], __float_as_uint(pa.y));
            PACK2(pp[2], __float_as_uint(pa.z));
            PACK2(pp[3], __float_as_uint(pa.w));
            PACK2(pp[4], __float_as_uint(pb.x));
            PACK2(pp[5], __float_as_uint(pb.y));
            PACK2(pp[6], __float_as_uint(pb.z));
            PACK2(pp[7], __float_as_uint(pb.w));
            ulonglong2 wA = *(const ulonglong2*)&whs[jj][f_idx * 4];
            ulonglong2 wB = *(const ulonglong2*)&whs[jj][128 + f_idx * 4];
            unsigned long long w2[4] = {wA.x, wA.y, wB.x, wB.y};
#pragma unroll
            for (int di = 0; di < 8; di++) {
                FFMA2(acc2[di][0], pp[di], w2[0], acc2[di][0]);
                FFMA2(acc2[di][1], pp[di], w2[1], acc2[di][1]);
                FFMA2(acc2[di][2], pp[di], w2[2], acc2[di][2]);
                FFMA2(acc2[di][3], pp[di], w2[3], acc2[di][3]);
            }
        }
    }

    // epilogue: normalize by Z, LayerNorm over F, gamma/beta, exact GELU
    float4 g0 = *(const float4*)&gamma[f_idx * 4];
    float4 g1 = *(const float4*)&gamma[128 + f_idx * 4];
    float4 bb0 = *(const float4*)&beta[f_idx * 4];
    float4 bb1 = *(const float4*)&beta[128 + f_idx * 4];
    float gv[8] = {g0.x, g0.y, g0.z, g0.w, g1.x, g1.y, g1.z, g1.w};
    float bv[8] = {bb0.x, bb0.y, bb0.z, bb0.w, bb1.x, bb1.y, bb1.z, bb1.w};

    float* outbase = out + (size_t)b * Nn * Fd + (size_t)(i0 + i_idx * 8) * Fd;

#pragma unroll
    for (int di = 0; di < 8; di++) {
        float invZ = 1.f / zsum[i_idx * 8 + di];
        float x[8];
#pragma unroll
        for (int k = 0; k < 4; k++) {
            unsigned int lo = (unsigned int)(acc2[di][k] & 0xffffffffull);
            unsigned int hi = (unsigned int)(acc2[di][k] >> 32);
            x[2 * k + 0] = __uint_as_float(lo) * invZ;
            x[2 * k + 1] = __uint_as_float(hi) * invZ;
        }
        float s = 0.f;
#pragma unroll
        for (int fj = 0; fj < 8; fj++) s += x[fj];
#pragma unroll
        for (int o = 16; o; o >>= 1) s += __shfl_xor_sync(0xffffffffu, s, o);
        float mu = s * (1.f / 256.f);
        float vs = 0.f;
#pragma unroll
        for (int fj = 0; fj < 8; fj++) { float d = x[fj] - mu; vs += d * d; }
#pragma unroll
        for (int o = 16; o; o >>= 1) vs += __shfl_xor_sync(0xffffffffu, vs, o);
        float rstd = rsqrtf(vs * (1.f / 256.f) + 1e-5f);

        float r0[4], r1[4];
#pragma unroll
        for (int fj = 0; fj < 8; fj++) {
            float y = (x[fj] - mu) * rstd * gv[fj] + bv[fj];
            float ge = 0.5f * y * (1.f + erff(y * 0.7071067811865475f));
            if (fj < 4) r0[fj] = ge; else r1[fj - 4] = ge;
        }
        *(float4*)&outbase[di * 256 + f_idx * 4] = make_float4(r0[0], r0[1], r0[2], r0[3]);
        *(float4*)&outbase[di * 256 + 128 + f_idx * 4] = make_float4(r1[0], r1[1], r1[2], r1[3]);
    }
}

// ---------------------------------------------------------------------------
extern "C" void kernel_launch(void* const* d_in, const int* in_sizes, int n_in,
                              void* d_out, int out_size) {
    const float* h     = (const float*)d_in[0];
    const float* adj   = (const float*)d_in[1];
    const float* W     = (const float*)d_in[2];
    const float* a     = (const float*)d_in[3];
    const float* gamma = (const float*)d_in[4];
    const float* beta  = (const float*)d_in[5];
    float* out = (float*)d_out;

    gemm1_kernel<<<dim3(256, 4), 256>>>(h, W);          // Wh = h @ W
    score_kernel<<<2048, 256>>>(a);                      // s1,s2 -> factored exps
    attn_kernel<<<dim3(32, 8), 256>>>(adj, gamma, beta, out);
}

// round 2
// speedup vs baseline: 1.0551x; 1.0551x over previous
#include <cuda_runtime.h>
#include <cstdint>

#define Bsz 8
#define Nn 2048
#define Fd 256

// scratch (device globals; no allocation allowed)
__device__ float g_Wh[Bsz * Nn * Fd];          // 64 MB
__device__ float g_E1p[Bsz * Nn];
__device__ float g_E1n[Bsz * Nn];
__device__ float g_E2p[Bsz * Nn];
__device__ float g_E2n[Bsz * Nn];

// packed fp32x2 FMA (Blackwell FFMA2)
#define FFMA2(d, a, b, c) \
    asm("fma.rn.f32x2 %0, %1, %2, %3;" : "=l"(d) : "l"(a), "l"(b), "l"(c))
#define PACK2(out, x) \
    asm("mov.b64 %0, {%1, %1};" : "=l"(out) : "r"(x))

// ---------------------------------------------------------------------------
// K1: Wh = h @ W   (16384 x 256 x 256 GEMM, fp32)
// ---------------------------------------------------------------------------
__global__ __launch_bounds__(256) void gemm1_kernel(const float* __restrict__ h,
                                                    const float* __restrict__ W) {
    __shared__ float As[16][68];   // transposed A tile [k][i]
    __shared__ float Bs[16][64];   // [k][f]
    int tid = threadIdx.x;
    int i0 = blockIdx.x * 64;
    int f0 = blockIdx.y * 64;
    int tx = tid & 15;        // f subtile
    int ty = tid >> 4;        // i subtile
    float acc[4][4] = {};
    for (int k0 = 0; k0 < 256; k0 += 16) {
        {
            int r = tid >> 2, c4 = (tid & 3) * 4;
            float4 v = *(const float4*)&h[(size_t)(i0 + r) * 256 + k0 + c4];
            As[c4 + 0][r] = v.x; As[c4 + 1][r] = v.y;
            As[c4 + 2][r] = v.z; As[c4 + 3][r] = v.w;
        }
        {
            int r = tid >> 4, c4 = (tid & 15) * 4;
            *(float4*)&Bs[r][c4] = *(const float4*)&W[(size_t)(k0 + r) * 256 + f0 + c4];
        }
        __syncthreads();
#pragma unroll
        for (int k = 0; k < 16; k++) {
            float4 a = *(const float4*)&As[k][ty * 4];
            float4 b = *(const float4*)&Bs[k][tx * 4];
            float av[4] = {a.x, a.y, a.z, a.w};
            float bv[4] = {b.x, b.y, b.z, b.w};
#pragma unroll
            for (int ii = 0; ii < 4; ii++)
#pragma unroll
                for (int jj = 0; jj < 4; jj++)
                    acc[ii][jj] += av[ii] * bv[jj];
        }
        __syncthreads();
    }
#pragma unroll
    for (int ii = 0; ii < 4; ii++) {
        float4 v = make_float4(acc[ii][0], acc[ii][1], acc[ii][2], acc[ii][3]);
        *(float4*)&g_Wh[(size_t)(i0 + ty * 4 + ii) * 256 + f0 + tx * 4] = v;
    }
}

// ---------------------------------------------------------------------------
// K2: per-row scores s1,s2 and the 4 factored exponentials
// ---------------------------------------------------------------------------
__global__ __launch_bounds__(256) void score_kernel(const float* __restrict__ a) {
    int row = blockIdx.x * 8 + (threadIdx.x >> 5);   // one warp per row
    int lane = threadIdx.x & 31;
    const float* wh = &g_Wh[(size_t)row * 256];
    float s1 = 0.f, s2 = 0.f;
#pragma unroll
    for (int c = 0; c < 8; c++) {
        int f = c * 32 + lane;
        float v = wh[f];
        s1 += v * a[f];
        s2 += v * a[256 + f];
    }
#pragma unroll
    for (int o = 16; o; o >>= 1) {
        s1 += __shfl_xor_sync(0xffffffffu, s1, o);
        s2 += __shfl_xor_sync(0xffffffffu, s2, o);
    }
    if (lane == 0) {
        g_E1p[row] = expf(s1);
        g_E1n[row] = expf(0.2f * s1);
        g_E2p[row] = expf(s2);
        g_E2n[row] = expf(0.2f * s2);
    }
}

// ---------------------------------------------------------------------------
// K3: fused masked-softmax attention aggregate + LayerNorm + exact GELU
//     block: 64 rows (i) x 256 cols (f), loops over j in tiles of 32
// ---------------------------------------------------------------------------
__global__ __launch_bounds__(256, 2) void attn_kernel(const float* __restrict__ adj,
                                                      const float* __restrict__ gamma,
                                                      const float* __restrict__ beta,
                                                      float* __restrict__ out) {
    __shared__ float whs[32][256];   // Wh tile [j][f]  32KB
    __shared__ float ps[32][68];     // p tile transposed [j][i], padded
    __shared__ float zsum[64];
    __shared__ float e1p_s[64], e1n_s[64];

    int tid = threadIdx.x;
    int b = blockIdx.y;
    int i0 = blockIdx.x * 64;

    if (tid < 64) {
        e1p_s[tid] = g_E1p[b * Nn + i0 + tid];
        e1n_s[tid] = g_E1n[b * Nn + i0 + tid];
        zsum[tid] = 0.f;
    }

    int f_idx = tid & 31;     // thread covers f = f_idx*4..+3 and 128+f_idx*4..+3
    int i_idx = tid >> 5;     // thread covers rows i_idx*8 .. i_idx*8+7

    unsigned long long acc2[8][4];
#pragma unroll
    for (int di = 0; di < 8; di++)
#pragma unroll
        for (int k = 0; k < 4; k++) acc2[di][k] = 0ull;

    const float* whbase = &g_Wh[(size_t)b * Nn * Fd];
    const float* adjbase = &adj[(size_t)b * Nn * Nn + (size_t)i0 * Nn];
    const float* e2p = &g_E2p[b * Nn];
    const float* e2n = &g_E2n[b * Nn];

    int ii = tid >> 3;              // 0..31
    int jj4 = (tid & 7) * 4;        // 0..28

    for (int j0 = 0; j0 < Nn; j0 += 32) {
        __syncthreads();   // prior FFMA phase done; also covers init on iter 0

        // load Wh tile (32 x 256 floats, coalesced float4)
#pragma unroll
        for (int k = 0; k < 8; k++) {
            int idx = tid + k * 256;       // float4 index
            int r = idx >> 6;
            int c = idx & 63;
            *(float4*)&whs[r][c * 4] =
                *(const float4*)&whbase[(size_t)(j0 + r) * 256 + c * 4];
        }

        // compute unnormalized p tile (64 x 32), two row-halves per thread
        float e2pv[4], e2nv[4];
#pragma unroll
        for (int c = 0; c < 4; c++) {
            e2pv[c] = e2p[j0 + jj4 + c];
            e2nv[c] = e2n[j0 + jj4 + c];
        }
#pragma unroll
        for (int half = 0; half < 2; half++) {
            int iR = ii + half * 32;
            float4 av = *(const float4*)&adjbase[(size_t)iR * Nn + j0 + jj4];
            float adjv[4] = {av.x, av.y, av.z, av.w};
            float e1pv = e1p_s[iR], e1nv = e1n_s[iR];
            float zpart = 0.f;
            float pv[4];
#pragma unroll
            for (int c = 0; c < 4; c++) {
                float t = e1pv * e2pv[c];
                float v = (t > 1.f) ? t : e1nv * e2nv[c];
                float p = adjv[c] * v;
                pv[c] = p;
                zpart += p;
            }
            zpart += __shfl_xor_sync(0xffffffffu, zpart, 1);
            zpart += __shfl_xor_sync(0xffffffffu, zpart, 2);
            zpart += __shfl_xor_sync(0xffffffffu, zpart, 4);
#pragma unroll
            for (int c = 0; c < 4; c++) ps[jj4 + c][iR] = pv[c];
            if ((tid & 7) == 0) zsum[iR] += zpart;
        }
        __syncthreads();

        // accumulate: acc[i][f] += p[i][j] * Wh[j][f]   (packed f32x2)
#pragma unroll 8
        for (int jj = 0; jj < 32; jj++) {
            float4 pa = *(const float4*)&ps[jj][i_idx * 8];
            float4 pb = *(const float4*)&ps[jj][i_idx * 8 + 4];
            unsigned long long pp[8];
            PACK2(pp[0], __float_as_uint(pa.x));
            PACK2(pp[1], __float_as_uint(pa.y));
            PACK2(pp[2], __float_as_uint(pa.z));
            PACK2(pp[3], __float_as_uint(pa.w));
            PACK2(pp[4], __float_as_uint(pb.x));
            PACK2(pp[5], __float_as_uint(pb.y));
            PACK2(pp[6], __float_as_uint(pb.z));
            PACK2(pp[7], __float_as_uint(pb.w));
            ulonglong2 wA = *(const ulonglong2*)&whs[jj][f_idx * 4];
            ulonglong2 wB = *(const ulonglong2*)&whs[jj][128 + f_idx * 4];
            unsigned long long w2[4] = {wA.x, wA.y, wB.x, wB.y};
#pragma unroll
            for (int di = 0; di < 8; di++) {
                FFMA2(acc2[di][0], pp[di], w2[0], acc2[di][0]);
                FFMA2(acc2[di][1], pp[di], w2[1], acc2[di][1]);
                FFMA2(acc2[di][2], pp[di], w2[2], acc2[di][2]);
                FFMA2(acc2[di][3], pp[di], w2[3], acc2[di][3]);
            }
        }
    }

    // epilogue: normalize by Z, LayerNorm over F, gamma/beta, exact GELU
    float4 g0 = *(const float4*)&gamma[f_idx * 4];
    float4 g1 = *(const float4*)&gamma[128 + f_idx * 4];
    float4 bb0 = *(const float4*)&beta[f_idx * 4];
    float4 bb1 = *(const float4*)&beta[128 + f_idx * 4];
    float gv[8] = {g0.x, g0.y, g0.z, g0.w, g1.x, g1.y, g1.z, g1.w};
    float bv[8] = {bb0.x, bb0.y, bb0.z, bb0.w, bb1.x, bb1.y, bb1.z, bb1.w};

    float* outbase = out + (size_t)b * Nn * Fd + (size_t)(i0 + i_idx * 8) * Fd;

#pragma unroll
    for (int di = 0; di < 8; di++) {
        float invZ = 1.f / zsum[i_idx * 8 + di];
        float x[8];
#pragma unroll
        for (int k = 0; k < 4; k++) {
            unsigned int lo = (unsigned int)(acc2[di][k] & 0xffffffffull);
            unsigned int hi = (unsigned int)(acc2[di][k] >> 32);
            x[2 * k + 0] = __uint_as_float(lo) * invZ;
            x[2 * k + 1] = __uint_as_float(hi) * invZ;
        }
        float s = 0.f;
#pragma unroll
        for (int fj = 0; fj < 8; fj++) s += x[fj];
#pragma unroll
        for (int o = 16; o; o >>= 1) s += __shfl_xor_sync(0xffffffffu, s, o);
        float mu = s * (1.f / 256.f);
        float vs = 0.f;
#pragma unroll
        for (int fj = 0; fj < 8; fj++) { float d = x[fj] - mu; vs += d * d; }
#pragma unroll
        for (int o = 16; o; o >>= 1) vs += __shfl_xor_sync(0xffffffffu, vs, o);
        float rstd = rsqrtf(vs * (1.f / 256.f) + 1e-5f);

        float r0[4], r1[4];
#pragma unroll
        for (int fj = 0; fj < 8; fj++) {
            float y = (x[fj] - mu) * rstd * gv[fj] + bv[fj];
            float ge = 0.5f * y * (1.f + erff(y * 0.7071067811865475f));
            if (fj < 4) r0[fj] = ge; else r1[fj - 4] = ge;
        }
        *(float4*)&outbase[di * 256 + f_idx * 4] = make_float4(r0[0], r0[1], r0[2], r0[3]);
        *(float4*)&outbase[di * 256 + 128 + f_idx * 4] = make_float4(r1[0], r1[1], r1[2], r1[3]);
    }
}

// ---------------------------------------------------------------------------
extern "C" void kernel_launch(void* const* d_in, const int* in_sizes, int n_in,
                              void* d_out, int out_size) {
    const float* h     = (const float*)d_in[0];
    const float* adj   = (const float*)d_in[1];
    const float* W     = (const float*)d_in[2];
    const float* a     = (const float*)d_in[3];
    const float* gamma = (const float*)d_in[4];
    const float* beta  = (const float*)d_in[5];
    float* out = (float*)d_out;

    gemm1_kernel<<<dim3(256, 4), 256>>>(h, W);          // Wh = h @ W
    score_kernel<<<2048, 256>>>(a);                      // s1,s2 -> factored exps
    attn_kernel<<<dim3(32, 8), 256>>>(adj, gamma, beta, out);
}

// round 6
// speedup vs baseline: 1.3318x; 1.2623x over previous
#include <cuda_runtime.h>
#include <cuda_bf16.h>
#include <cstdint>

#define Bsz 8
#define Nn 2048
#define Fd 256
#define KC 32
#define NIT (Nn / KC)   // 64 chunks per pass

// -------- device scratch (no allocation allowed) --------
__device__ float g_Wh[(size_t)Bsz * Nn * Fd];
__device__ float g_S1[Bsz * Nn];
__device__ float g_S2[Bsz * Nn];
__device__ float g_E1p[Bsz * Nn];
__device__ float g_E1n[Bsz * Nn];
__device__ float g_E2p[Bsz * Nn];
__device__ float g_E2n[Bsz * Nn];
// X arrays, layout [b][j][f], bf16
__device__ unsigned short g_X1h[(size_t)Bsz * Nn * Fd];
__device__ unsigned short g_X1l[(size_t)Bsz * Nn * Fd];
__device__ unsigned short g_X2h[(size_t)Bsz * Nn * Fd];
__device__ unsigned short g_X2l[(size_t)Bsz * Nn * Fd];

// -------- helpers --------
__device__ __forceinline__ uint32_t smem_u32(const void* p) {
    uint32_t a;
    asm("{ .reg .u64 t; cvta.to.shared.u64 t, %1; cvt.u32.u64 %0, t; }" : "=r"(a) : "l"(p));
    return a;
}
__device__ __forceinline__ void cp_async16(uint32_t dst, const void* src) {
    asm volatile("cp.async.cg.shared.global [%0], [%1], 16;" :: "r"(dst), "l"(src) : "memory");
}
__device__ __forceinline__ void cp_commit() {
    asm volatile("cp.async.commit_group;" ::: "memory");
}
__device__ __forceinline__ void cp_wait1() {
    asm volatile("cp.async.wait_group 1;" ::: "memory");
}
__device__ __forceinline__ void ldsm4(uint32_t* r, uint32_t addr) {
    asm volatile("ldmatrix.sync.aligned.m8n8.x4.shared.b16 {%0,%1,%2,%3}, [%4];"
                 : "=r"(r[0]), "=r"(r[1]), "=r"(r[2]), "=r"(r[3]) : "r"(addr));
}
__device__ __forceinline__ void ldsm4t(uint32_t* r, uint32_t addr) {
    asm volatile("ldmatrix.sync.aligned.m8n8.x4.trans.shared.b16 {%0,%1,%2,%3}, [%4];"
                 : "=r"(r[0]), "=r"(r[1]), "=r"(r[2]), "=r"(r[3]) : "r"(addr));
}
__device__ __forceinline__ void mma16816(float* d, const uint32_t* a, uint32_t b0, uint32_t b1) {
    asm volatile(
        "mma.sync.aligned.m16n8k16.row.col.f32.bf16.bf16.f32 "
        "{%0,%1,%2,%3}, {%4,%5,%6,%7}, {%8,%9}, {%0,%1,%2,%3};"
        : "+f"(d[0]), "+f"(d[1]), "+f"(d[2]), "+f"(d[3])
        : "r"(a[0]), "r"(a[1]), "r"(a[2]), "r"(a[3]), "r"(b0), "r"(b1));
}
__device__ __forceinline__ uint32_t bf16pair(float lo, float hi) {
    uint32_t r;
    asm("cvt.rn.bf16x2.f32 %0, %1, %2;" : "=r"(r) : "f"(hi), "f"(lo));
    return r;
}

// ---------------------------------------------------------------------------
// K1: Wh = h @ W  (fp32, known-good)
// ---------------------------------------------------------------------------
__global__ __launch_bounds__(256) void gemm1_kernel(const float* __restrict__ h,
                                                    const float* __restrict__ W) {
    __shared__ float As[16][68];
    __shared__ float Bs[16][64];
    int tid = threadIdx.x;
    int i0 = blockIdx.x * 64, f0 = blockIdx.y * 64;
    int tx = tid & 15, ty = tid >> 4;
    float acc[4][4] = {};
    for (int k0 = 0; k0 < 256; k0 += 16) {
        {
            int r = tid >> 2, c4 = (tid & 3) * 4;
            float4 v = *(const float4*)&h[(size_t)(i0 + r) * 256 + k0 + c4];
            As[c4 + 0][r] = v.x; As[c4 + 1][r] = v.y;
            As[c4 + 2][r] = v.z; As[c4 + 3][r] = v.w;
        }
        {
            int r = tid >> 4, c4 = (tid & 15) * 4;
            *(float4*)&Bs[r][c4] = *(const float4*)&W[(size_t)(k0 + r) * 256 + f0 + c4];
        }
        __syncthreads();
#pragma unroll
        for (int k = 0; k < 16; k++) {
            float4 a = *(const float4*)&As[k][ty * 4];
            float4 b = *(const float4*)&Bs[k][tx * 4];
            float av[4] = {a.x, a.y, a.z, a.w};
            float bv[4] = {b.x, b.y, b.z, b.w};
#pragma unroll
            for (int ii = 0; ii < 4; ii++)
#pragma unroll
                for (int jj = 0; jj < 4; jj++) acc[ii][jj] += av[ii] * bv[jj];
        }
        __syncthreads();
    }
#pragma unroll
    for (int ii = 0; ii < 4; ii++)
        *(float4*)&g_Wh[(size_t)(i0 + ty * 4 + ii) * 256 + f0 + tx * 4] =
            make_float4(acc[ii][0], acc[ii][1], acc[ii][2], acc[ii][3]);
}

// ---------------------------------------------------------------------------
// K2: scores + factored exps
// ---------------------------------------------------------------------------
__global__ __launch_bounds__(256) void score_kernel(const float* __restrict__ a) {
    int row = blockIdx.x * 8 + (threadIdx.x >> 5);
    int lane = threadIdx.x & 31;
    const float* wh = &g_Wh[(size_t)row * 256];
    float s1 = 0.f, s2 = 0.f;
#pragma unroll
    for (int c = 0; c < 8; c++) {
        int f = c * 32 + lane;
        float v = wh[f];
        s1 += v * a[f];
        s2 += v * a[256 + f];
    }
#pragma unroll
    for (int o = 16; o; o >>= 1) {
        s1 += __shfl_xor_sync(0xffffffffu, s1, o);
        s2 += __shfl_xor_sync(0xffffffffu, s2, o);
    }
    if (lane == 0) {
        g_S1[row] = s1; g_S2[row] = s2;
        g_E1p[row] = expf(s1);  g_E1n[row] = expf(0.2f * s1);
        g_E2p[row] = expf(s2);  g_E2n[row] = expf(0.2f * s2);
    }
}

// ---------------------------------------------------------------------------
// K3: X1/X2 hi/lo bf16 split, elementwise (layout [b][j][f], same as Wh)
//     total float4 elements: Bsz*Nn*Fd/4 = 1048576 -> 4096 blocks x 256 thr
// ---------------------------------------------------------------------------
__global__ __launch_bounds__(256) void buildX_kernel() {
    size_t e4 = (size_t)blockIdx.x * 256 + threadIdx.x;   // float4 index
    size_t row = e4 >> 6;                                 // b*Nn + j
    float4 v = *(const float4*)&g_Wh[e4 * 4];
    float ep = g_E2p[row], en = g_E2n[row];
    float x1[4] = {v.x * ep, v.y * ep, v.z * ep, v.w * ep};
    float x2[4] = {v.x * en, v.y * en, v.z * en, v.w * en};
    float h1[4], h2[4];
#pragma unroll
    for (int k = 0; k < 4; k++) {
        h1[k] = __bfloat162float(__float2bfloat16(x1[k]));
        h2[k] = __bfloat162float(__float2bfloat16(x2[k]));
    }
    uint2 o;
    o.x = bf16pair(h1[0], h1[1]); o.y = bf16pair(h1[2], h1[3]);
    *(uint2*)&g_X1h[e4 * 4] = o;
    o.x = bf16pair(x1[0] - h1[0], x1[1] - h1[1]); o.y = bf16pair(x1[2] - h1[2], x1[3] - h1[3]);
    *(uint2*)&g_X1l[e4 * 4] = o;
    o.x = bf16pair(h2[0], h2[1]); o.y = bf16pair(h2[2], h2[3]);
    *(uint2*)&g_X2h[e4 * 4] = o;
    o.x = bf16pair(x2[0] - h2[0], x2[1] - h2[1]); o.y = bf16pair(x2[2] - h2[2], x2[3] - h2[3]);
    *(uint2*)&g_X2l[e4 * 4] = o;
}

// ---------------------------------------------------------------------------
// K4: HMMA masked attention + LayerNorm + exact GELU
//     CTA: 128 rows x 256 f, 512 threads (16 warps, 32x64 warp tiles)
// ---------------------------------------------------------------------------
#define XS_STRIDE 260
#define XOFF (128 * XS_STRIDE * 4)              // 133120
#define SLOT_BYTES 32768                        // hi+lo, 32 x 512B rows
#define MOFF (XOFF + 2 * SLOT_BYTES)            // 198656
#define MSTRIDE 80                              // mask row stride (bytes)
#define DYN_B (MOFF + 128 * MSTRIDE)            // 208896

__global__ void __launch_bounds__(512, 1)
attn_mma_kernel(const float* __restrict__ adj, const float* __restrict__ gamma,
                const float* __restrict__ beta, float* __restrict__ out) {
    extern __shared__ char dyn[];
    __shared__ float s1_s[128], e1p_s[128], e1n_s[128], z1_s[128], z2_s[128],
                     invz_s[128], mu_s[128], rs_s[128];

    const int tid = threadIdx.x;
    const int lane = tid & 31;
    const int wid = tid >> 5;
    const int wm = wid >> 2, wn = wid & 3;
    const int b = blockIdx.y;
    const int i0 = blockIdx.x * 128;

    const uint32_t smem = smem_u32(dyn);
    float* xs = (float*)dyn;
    const uint32_t mbase = smem + MOFF;
    const uint32_t xoff = smem + XOFF;

    if (tid < 128) {
        s1_s[tid]  = g_S1[b * Nn + i0 + tid];
        e1p_s[tid] = g_E1p[b * Nn + i0 + tid];
        e1n_s[tid] = g_E1n[b * Nn + i0 + tid];
    }
    __syncthreads();

    // ldmatrix per-lane address components
    const uint32_t aRowOff = (uint32_t)((32 * wm + ((lane >> 3) & 1) * 8 + (lane & 7)) * MSTRIDE
                                        + (lane >> 4) * 16);
    const int jb = ((lane >> 3) & 1) * 8 + (lane & 7);
    const int ub = 8 * wn + (lane >> 4);
    const int jsw = jb & 7;

    // mask-gen mapping: thread -> (row mi, j-quarter mq)
    const int mi = tid >> 2;
    const int mq = tid & 3;
    const float s1v = s1_s[mi];
    const float* adjrow = adj + ((size_t)b * Nn + i0 + mi) * Nn + mq * 8;
    const float* s2g  = g_S2  + b * Nn + mq * 8;
    const float* e2pg = g_E2p + b * Nn + mq * 8;
    const float* e2ng = g_E2n + b * Nn + mq * 8;
    const uint32_t mst = mbase + mi * MSTRIDE + mq * 16;

    float zp = 0.f, zn = 0.f;
    float dacc[2][8][4];

#pragma unroll 1
    for (int pass = 0; pass < 2; pass++) {
        const unsigned short* srcH =
            (pass == 0 ? g_X1h : g_X2h) + (size_t)b * Nn * Fd;
        const unsigned short* srcL =
            (pass == 0 ? g_X1l : g_X2l) + (size_t)b * Nn * Fd;

#pragma unroll
        for (int mt = 0; mt < 2; mt++)
#pragma unroll
            for (int n8 = 0; n8 < 8; n8++)
#pragma unroll
                for (int k = 0; k < 4; k++) dacc[mt][n8][k] = 0.f;

        // prologue: X chunk 0 -> slot 0; adj chunk 0 -> regs
        {
#pragma unroll
            for (int r = 0; r < 2; r++) {
                int e = tid + r * 512;
                int j = e >> 5, u = e & 31;
                uint32_t d = xoff + j * 512 + (((u ^ (j & 7))) << 4);
                const unsigned short* gs = srcH + (size_t)j * Fd + u * 8;
                const unsigned short* gl = srcL + (size_t)j * Fd + u * 8;
                cp_async16(d, gs);
                cp_async16(d + 16384, gl);
            }
            cp_commit();
        }
        float4 ajA = *(const float4*)&adjrow[0];
        float4 ajB = *(const float4*)&adjrow[4];

#pragma unroll 1
        for (int it = 0; it < NIT; it++) {
            __syncthreads();   // previous iter's SMEM reads complete

            // issue X(it+1) into the other slot
            if (it + 1 < NIT) {
                uint32_t dst = xoff + ((it + 1) & 1) * SLOT_BYTES;
                size_t grow = (size_t)((it + 1) * KC) * Fd;
#pragma unroll
                for (int r = 0; r < 2; r++) {
                    int e = tid + r * 512;
                    int j = e >> 5, u = e & 31;
                    uint32_t d = dst + j * 512 + (((u ^ (j & 7))) << 4);
                    cp_async16(d, srcH + grow + (size_t)j * Fd + u * 8);
                    cp_async16(d + 16384, srcL + grow + (size_t)j * Fd + u * 8);
                }
            }
            cp_commit();

            // mask generation for chunk it (from prefetched adj regs)
            {
                float av[8] = {ajA.x, ajA.y, ajA.z, ajA.w, ajB.x, ajB.y, ajB.z, ajB.w};
                float4 s2a = __ldg((const float4*)&s2g[it * KC]);
                float4 s2b = __ldg((const float4*)&s2g[it * KC + 4]);
                float s2v[8] = {s2a.x, s2a.y, s2a.z, s2a.w, s2b.x, s2b.y, s2b.z, s2b.w};
                uint32_t w[4] = {0, 0, 0, 0};
                if (pass == 0) {
                    float4 epa = __ldg((const float4*)&e2pg[it * KC]);
                    float4 epb = __ldg((const float4*)&e2pg[it * KC + 4]);
                    float4 ena = __ldg((const float4*)&e2ng[it * KC]);
                    float4 enb = __ldg((const float4*)&e2ng[it * KC + 4]);
                    float epv[8] = {epa.x, epa.y, epa.z, epa.w, epb.x, epb.y, epb.z, epb.w};
                    float env[8] = {ena.x, ena.y, ena.z, ena.w, enb.x, enb.y, enb.z, enb.w};
#pragma unroll
                    for (int k = 0; k < 8; k++) {
                        bool on = av[k] > 0.5f;
                        bool pos = (s1v + s2v[k]) > 0.f;
                        if (on && pos)  { w[k >> 1] |= 0x3F80u << ((k & 1) * 16); zp += epv[k]; }
                        if (on && !pos) zn += env[k];
                    }
                } else {
#pragma unroll
                    for (int k = 0; k < 8; k++) {
                        bool on = av[k] > 0.5f;
                        bool pos = (s1v + s2v[k]) > 0.f;
                        if (on && !pos) w[k >> 1] |= 0x3F80u << ((k & 1) * 16);
                    }
                }
                asm volatile("st.shared.v4.b32 [%0], {%1,%2,%3,%4};"
                             :: "r"(mst), "r"(w[0]), "r"(w[1]), "r"(w[2]), "r"(w[3]) : "memory");
            }

            // prefetch adj(it+1)
            if (it + 1 < NIT) {
                ajA = *(const float4*)&adjrow[(it + 1) * KC];
                ajB = *(const float4*)&adjrow[(it + 1) * KC + 4];
            }

            cp_wait1();        // X(it) landed
            __syncthreads();   // masks + X visible to all warps

            // MMA on chunk it
            const uint32_t xb = xoff + (it & 1) * SLOT_BYTES;
#pragma unroll
            for (int ks = 0; ks < 2; ks++) {
                uint32_t a0[4], a1[4];
                ldsm4(a0, mbase + aRowOff + ks * 32);
                ldsm4(a1, mbase + aRowOff + 16 * MSTRIDE + ks * 32);
                const int j = jb + ks * 16;
                const uint32_t rowb = xb + j * 512;
#pragma unroll
                for (int ng = 0; ng < 4; ng++) {
                    const int u = ub + 2 * ng;
                    const uint32_t addrH = rowb + (((u ^ jsw)) << 4);
                    uint32_t bh[4], bl[4];
                    ldsm4t(bh, addrH);
                    ldsm4t(bl, addrH + 16384);
                    mma16816(dacc[0][2 * ng],     a0, bh[0], bh[1]);
                    mma16816(dacc[0][2 * ng + 1], a0, bh[2], bh[3]);
                    mma16816(dacc[1][2 * ng],     a1, bh[0], bh[1]);
                    mma16816(dacc[1][2 * ng + 1], a1, bh[2], bh[3]);
                    mma16816(dacc[0][2 * ng],     a0, bl[0], bl[1]);
                    mma16816(dacc[0][2 * ng + 1], a0, bl[2], bl[3]);
                    mma16816(dacc[1][2 * ng],     a1, bl[0], bl[1]);
                    mma16816(dacc[1][2 * ng + 1], a1, bl[2], bl[3]);
                }
            }
        }

        const int r0 = 32 * wm + (lane >> 2);
        const int cb = 64 * wn + (lane & 3) * 2;

        if (pass == 0) {
            // finish Z, stage e1p*Y1 into xs
            zp += __shfl_xor_sync(0xffffffffu, zp, 1);
            zp += __shfl_xor_sync(0xffffffffu, zp, 2);
            zn += __shfl_xor_sync(0xffffffffu, zn, 1);
            zn += __shfl_xor_sync(0xffffffffu, zn, 2);
            if (mq == 0) { z1_s[mi] = zp; z2_s[mi] = zn; }
            __syncthreads();
            if (tid < 128)
                invz_s[tid] = 1.f / (e1p_s[tid] * z1_s[tid] + e1n_s[tid] * z2_s[tid]);
#pragma unroll
            for (int mt = 0; mt < 2; mt++) {
                int ra = r0 + 16 * mt;
                float ea = e1p_s[ra], eb = e1p_s[ra + 8];
#pragma unroll
                for (int n8 = 0; n8 < 8; n8++) {
                    int c = cb + 8 * n8;
                    *(float2*)&xs[ra * XS_STRIDE + c] =
                        make_float2(ea * dacc[mt][n8][0], ea * dacc[mt][n8][1]);
                    *(float2*)&xs[(ra + 8) * XS_STRIDE + c] =
                        make_float2(eb * dacc[mt][n8][2], eb * dacc[mt][n8][3]);
                }
            }
        } else {
            // combine, normalize
#pragma unroll
            for (int mt = 0; mt < 2; mt++) {
                int ra = r0 + 16 * mt;
                float ea = e1n_s[ra], eb = e1n_s[ra + 8];
                float iza = invz_s[ra], izb = invz_s[ra + 8];
#pragma unroll
                for (int n8 = 0; n8 < 8; n8++) {
                    int c = cb + 8 * n8;
                    float2 xa = *(const float2*)&xs[ra * XS_STRIDE + c];
                    float2 xb2 = *(const float2*)&xs[(ra + 8) * XS_STRIDE + c];
                    xa.x = (xa.x + ea * dacc[mt][n8][0]) * iza;
                    xa.y = (xa.y + ea * dacc[mt][n8][1]) * iza;
                    xb2.x = (xb2.x + eb * dacc[mt][n8][2]) * izb;
                    xb2.y = (xb2.y + eb * dacc[mt][n8][3]) * izb;
                    *(float2*)&xs[ra * XS_STRIDE + c] = xa;
                    *(float2*)&xs[(ra + 8) * XS_STRIDE + c] = xb2;
                }
            }
        }
    }
    __syncthreads();

    // LayerNorm stats: 4 threads per row
    {
        int row = tid >> 2, q = tid & 3;
        const float* xr = &xs[row * XS_STRIDE + q * 64];
        float sum = 0.f, ssq = 0.f;
#pragma unroll 8
        for (int k = 0; k < 64; k++) { float v = xr[k]; sum += v; ssq += v * v; }
        sum += __shfl_xor_sync(0xffffffffu, sum, 1);
        sum += __shfl_xor_sync(0xffffffffu, sum, 2);
        ssq += __shfl_xor_sync(0xffffffffu, ssq, 1);
        ssq += __shfl_xor_sync(0xffffffffu, ssq, 2);
        if (q == 0) {
            float mu = sum * (1.f / 256.f);
            float var = fmaxf(ssq * (1.f / 256.f) - mu * mu, 0.f);
            mu_s[row] = mu;
            rs_s[row] = rsqrtf(var + 1e-5f);
        }
    }
    __syncthreads();

    // gamma/beta + exact GELU, coalesced store (128 rows x 64 float4 = 8192)
    float* outb = out + ((size_t)b * Nn + i0) * Fd;
#pragma unroll 1
    for (int r = 0; r < 16; r++) {
        int u = tid + r * 512;
        int i = u >> 6;
        int c4 = (u & 63) * 4;
        float mu = mu_s[i], rs = rs_s[i];
        float4 xv = *(const float4*)&xs[i * XS_STRIDE + c4];
        float4 g = *(const float4*)&gamma[c4];
        float4 be = *(const float4*)&beta[c4];
        float x[4] = {xv.x, xv.y, xv.z, xv.w};
        float gv[4] = {g.x, g.y, g.z, g.w};
        float bv[4] = {be.x, be.y, be.z, be.w};
        float ov[4];
#pragma unroll
        for (int e = 0; e < 4; e++) {
            float y = (x[e] - mu) * rs * gv[e] + bv[e];
            ov[e] = 0.5f * y * (1.f + erff(y * 0.7071067811865475f));
        }
        *(float4*)&outb[(size_t)i * 256 + c4] = make_float4(ov[0], ov[1], ov[2], ov[3]);
    }
}

// ---------------------------------------------------------------------------
extern "C" void kernel_launch(void* const* d_in, const int* in_sizes, int n_in,
                              void* d_out, int out_size) {
    const float* h     = (const float*)d_in[0];
    const float* adj   = (const float*)d_in[1];
    const float* W     = (const float*)d_in[2];
    const float* a     = (const float*)d_in[3];
    const float* gamma = (const float*)d_in[4];
    const float* beta  = (const float*)d_in[5];
    float* out = (float*)d_out;

    cudaFuncSetAttribute(attn_mma_kernel,
                         cudaFuncAttributeMaxDynamicSharedMemorySize, DYN_B);

    gemm1_kernel<<<dim3(256, 4), 256>>>(h, W);
    score_kernel<<<2048, 256>>>(a);
    buildX_kernel<<<4096, 256>>>();
    attn_mma_kernel<<<dim3(16, 8), 512, DYN_B>>>(adj, gamma, beta, out);
}

// round 7
// speedup vs baseline: 1.4070x; 1.0565x over previous
#include <cuda_runtime.h>
#include <cuda_bf16.h>
#include <cstdint>

#define Bsz 8
#define Nn 2048
#define Fd 256
#define KC 32
#define NIT (Nn / KC)   // 64 chunks per pass

// -------- device scratch (no allocation allowed) --------
__device__ float g_Wh[(size_t)Bsz * Nn * Fd];      // later reused as Y1 scratch
__device__ float g_S1[Bsz * Nn];
__device__ float g_S2[Bsz * Nn];
__device__ float g_E1p[Bsz * Nn];
__device__ float g_E1n[Bsz * Nn];
__device__ float g_E2p[Bsz * Nn];
__device__ float g_E2n[Bsz * Nn];
__device__ float g_Z1[Bsz * Nn];
__device__ float g_Z2[Bsz * Nn];
// X arrays, layout [b][j][f], bf16
__device__ unsigned short g_X1h[(size_t)Bsz * Nn * Fd];
__device__ unsigned short g_X1l[(size_t)Bsz * Nn * Fd];
__device__ unsigned short g_X2h[(size_t)Bsz * Nn * Fd];
__device__ unsigned short g_X2l[(size_t)Bsz * Nn * Fd];
// packed bit masks: [row][64] u32 (bit l of word k = mask at j = k*32+l)
__device__ uint32_t g_M1[(size_t)Bsz * Nn * 64];
__device__ uint32_t g_M2[(size_t)Bsz * Nn * 64];

// -------- helpers --------
__device__ __forceinline__ uint32_t smem_u32(const void* p) {
    uint32_t a;
    asm("{ .reg .u64 t; cvta.to.shared.u64 t, %1; cvt.u32.u64 %0, t; }" : "=r"(a) : "l"(p));
    return a;
}
__device__ __forceinline__ void cp_async16(uint32_t dst, const void* src) {
    asm volatile("cp.async.cg.shared.global [%0], [%1], 16;" :: "r"(dst), "l"(src) : "memory");
}
__device__ __forceinline__ void cp_commit() {
    asm volatile("cp.async.commit_group;" ::: "memory");
}
__device__ __forceinline__ void cp_wait1() {
    asm volatile("cp.async.wait_group 1;" ::: "memory");
}
__device__ __forceinline__ void ldsm4(uint32_t* r, uint32_t addr) {
    asm volatile("ldmatrix.sync.aligned.m8n8.x4.shared.b16 {%0,%1,%2,%3}, [%4];"
                 : "=r"(r[0]), "=r"(r[1]), "=r"(r[2]), "=r"(r[3]) : "r"(addr));
}
__device__ __forceinline__ void ldsm4t(uint32_t* r, uint32_t addr) {
    asm volatile("ldmatrix.sync.aligned.m8n8.x4.trans.shared.b16 {%0,%1,%2,%3}, [%4];"
                 : "=r"(r[0]), "=r"(r[1]), "=r"(r[2]), "=r"(r[3]) : "r"(addr));
}
__device__ __forceinline__ void mma16816(float* d, const uint32_t* a, uint32_t b0, uint32_t b1) {
    asm volatile(
        "mma.sync.aligned.m16n8k16.row.col.f32.bf16.bf16.f32 "
        "{%0,%1,%2,%3}, {%4,%5,%6,%7}, {%8,%9}, {%0,%1,%2,%3};"
        : "+f"(d[0]), "+f"(d[1]), "+f"(d[2]), "+f"(d[3])
        : "r"(a[0]), "r"(a[1]), "r"(a[2]), "r"(a[3]), "r"(b0), "r"(b1));
}
__device__ __forceinline__ uint32_t bf16pair(float lo, float hi) {
    uint32_t r;
    asm("cvt.rn.bf16x2.f32 %0, %1, %2;" : "=r"(r) : "f"(hi), "f"(lo));
    return r;
}

// ---------------------------------------------------------------------------
// K1: Wh = h @ W  (fp32, known-good)
// ---------------------------------------------------------------------------
__global__ __launch_bounds__(256) void gemm1_kernel(const float* __restrict__ h,
                                                    const float* __restrict__ W) {
    __shared__ float As[16][68];
    __shared__ float Bs[16][64];
    int tid = threadIdx.x;
    int i0 = blockIdx.x * 64, f0 = blockIdx.y * 64;
    int tx = tid & 15, ty = tid >> 4;
    float acc[4][4] = {};
    for (int k0 = 0; k0 < 256; k0 += 16) {
        {
            int r = tid >> 2, c4 = (tid & 3) * 4;
            float4 v = *(const float4*)&h[(size_t)(i0 + r) * 256 + k0 + c4];
            As[c4 + 0][r] = v.x; As[c4 + 1][r] = v.y;
            As[c4 + 2][r] = v.z; As[c4 + 3][r] = v.w;
        }
        {
            int r = tid >> 4, c4 = (tid & 15) * 4;
            *(float4*)&Bs[r][c4] = *(const float4*)&W[(size_t)(k0 + r) * 256 + f0 + c4];
        }
        __syncthreads();
#pragma unroll
        for (int k = 0; k < 16; k++) {
            float4 a = *(const float4*)&As[k][ty * 4];
            float4 b = *(const float4*)&Bs[k][tx * 4];
            float av[4] = {a.x, a.y, a.z, a.w};
            float bv[4] = {b.x, b.y, b.z, b.w};
#pragma unroll
            for (int ii = 0; ii < 4; ii++)
#pragma unroll
                for (int jj = 0; jj < 4; jj++) acc[ii][jj] += av[ii] * bv[jj];
        }
        __syncthreads();
    }
#pragma unroll
    for (int ii = 0; ii < 4; ii++)
        *(float4*)&g_Wh[(size_t)(i0 + ty * 4 + ii) * 256 + f0 + tx * 4] =
            make_float4(acc[ii][0], acc[ii][1], acc[ii][2], acc[ii][3]);
}

// ---------------------------------------------------------------------------
// K2: scores + factored exps
// ---------------------------------------------------------------------------
__global__ __launch_bounds__(256) void score_kernel(const float* __restrict__ a) {
    int row = blockIdx.x * 8 + (threadIdx.x >> 5);
    int lane = threadIdx.x & 31;
    const float* wh = &g_Wh[(size_t)row * 256];
    float s1 = 0.f, s2 = 0.f;
#pragma unroll
    for (int c = 0; c < 8; c++) {
        int f = c * 32 + lane;
        float v = wh[f];
        s1 += v * a[f];
        s2 += v * a[256 + f];
    }
#pragma unroll
    for (int o = 16; o; o >>= 1) {
        s1 += __shfl_xor_sync(0xffffffffu, s1, o);
        s2 += __shfl_xor_sync(0xffffffffu, s2, o);
    }
    if (lane == 0) {
        g_S1[row] = s1; g_S2[row] = s2;
        g_E1p[row] = expf(s1);  g_E1n[row] = expf(0.2f * s1);
        g_E2p[row] = expf(s2);  g_E2n[row] = expf(0.2f * s2);
    }
}

// ---------------------------------------------------------------------------
// K3: X1/X2 hi/lo bf16 split (4096 blocks x 256 thr)
// ---------------------------------------------------------------------------
__global__ __launch_bounds__(256) void buildX_kernel() {
    size_t e4 = (size_t)blockIdx.x * 256 + threadIdx.x;   // float4 index
    size_t row = e4 >> 6;                                 // b*Nn + j
    float4 v = *(const float4*)&g_Wh[e4 * 4];
    float ep = g_E2p[row], en = g_E2n[row];
    float x1[4] = {v.x * ep, v.y * ep, v.z * ep, v.w * ep};
    float x2[4] = {v.x * en, v.y * en, v.z * en, v.w * en};
    float h1[4], h2[4];
#pragma unroll
    for (int k = 0; k < 4; k++) {
        h1[k] = __bfloat162float(__float2bfloat16(x1[k]));
        h2[k] = __bfloat162float(__float2bfloat16(x2[k]));
    }
    uint2 o;
    o.x = bf16pair(h1[0], h1[1]); o.y = bf16pair(h1[2], h1[3]);
    *(uint2*)&g_X1h[e4 * 4] = o;
    o.x = bf16pair(x1[0] - h1[0], x1[1] - h1[1]); o.y = bf16pair(x1[2] - h1[2], x1[3] - h1[3]);
    *(uint2*)&g_X1l[e4 * 4] = o;
    o.x = bf16pair(h2[0], h2[1]); o.y = bf16pair(h2[2], h2[3]);
    *(uint2*)&g_X2h[e4 * 4] = o;
    o.x = bf16pair(x2[0] - h2[0], x2[1] - h2[1]); o.y = bf16pair(x2[2] - h2[2], x2[3] - h2[3]);
    *(uint2*)&g_X2l[e4 * 4] = o;
}

// ---------------------------------------------------------------------------
// K4: packed bit masks + Z row sums (one warp per row)
// ---------------------------------------------------------------------------
__global__ __launch_bounds__(256) void mask_kernel(const float* __restrict__ adj) {
    int row = blockIdx.x * 8 + (threadIdx.x >> 5);   // 0..16383
    int lane = threadIdx.x & 31;
    int b = row >> 11;
    const float* ar = adj + (size_t)row * Nn;
    const float* s2g  = g_S2  + b * Nn;
    const float* e2pg = g_E2p + b * Nn;
    const float* e2ng = g_E2n + b * Nn;
    float s1v = g_S1[row];
    float z1 = 0.f, z2 = 0.f;
    uint32_t w1lo = 0, w1hi = 0, w2lo = 0, w2hi = 0;
#pragma unroll 4
    for (int k = 0; k < 64; k++) {
        int j = k * 32 + lane;
        bool on = ar[j] > 0.5f;
        bool pos = (s1v + s2g[j]) > 0.f;
        bool m1 = on && pos, m2 = on && !pos;
        uint32_t b1 = __ballot_sync(0xffffffffu, m1);
        uint32_t b2 = __ballot_sync(0xffffffffu, m2);
        if (m1) z1 += e2pg[j];
        if (m2) z2 += e2ng[j];
        if ((k & 31) == lane) {
            if (k < 32) { w1lo = b1; w2lo = b2; }
            else        { w1hi = b1; w2hi = b2; }
        }
    }
#pragma unroll
    for (int o = 16; o; o >>= 1) {
        z1 += __shfl_xor_sync(0xffffffffu, z1, o);
        z2 += __shfl_xor_sync(0xffffffffu, z2, o);
    }
    g_M1[(size_t)row * 64 + lane] = w1lo;
    g_M1[(size_t)row * 64 + 32 + lane] = w1hi;
    g_M2[(size_t)row * 64 + lane] = w2lo;
    g_M2[(size_t)row * 64 + 32 + lane] = w2hi;
    if (lane == 0) { g_Z1[row] = z1; g_Z2[row] = z2; }
}

// ---------------------------------------------------------------------------
// K5: HMMA masked attention + LayerNorm + exact GELU
//     CTA: 64 rows x 256 f, 256 threads (8 warps, 32x64 warp tiles), 2 CTA/SM
// ---------------------------------------------------------------------------
#define ROWS 64
#define XS_STRIDE 260
#define SLOT_BYTES 32768                   // hi(16K)+lo(16K), 32 x 512B rows
#define MBUF_OFF (2 * SLOT_BYTES)          // 65536, single mask buffer
#define MSTRIDE 80
#define POFF (MBUF_OFF + ROWS * MSTRIDE)   // 70656, packed masks 16 KB
#define DYN_B (POFF + 4096 * 4)            // 87040

__global__ void __launch_bounds__(256, 2)
attn_mma_kernel(const float* __restrict__ gamma, const float* __restrict__ beta,
                float* __restrict__ out) {
    extern __shared__ char dyn[];
    __shared__ float e1p_s[ROWS], e1n_s[ROWS], invz_s[ROWS], mu_s[ROWS], rs_s[ROWS];

    const int tid = threadIdx.x;
    const int lane = tid & 31;
    const int wid = tid >> 5;
    const int wm = wid >> 2, wn = wid & 3;     // wm 0..1, wn 0..3
    const int b = blockIdx.y;
    const int i0 = blockIdx.x * ROWS;

    const uint32_t smem = smem_u32(dyn);
    float* xs = (float*)dyn;                    // overlays main-loop region post-loop
    const uint32_t mbuf = smem + MBUF_OFF;
    uint32_t* packed_s = (uint32_t*)(dyn + POFF);

    if (tid < ROWS) {
        float e1p = g_E1p[b * Nn + i0 + tid];
        float e1n = g_E1n[b * Nn + i0 + tid];
        e1p_s[tid] = e1p;
        e1n_s[tid] = e1n;
        invz_s[tid] = 1.f / (e1p * g_Z1[b * Nn + i0 + tid] +
                             e1n * g_Z2[b * Nn + i0 + tid]);
    }

    // ldmatrix per-lane address components (proven layout)
    const uint32_t aRowOff = (uint32_t)((32 * wm + ((lane >> 3) & 1) * 8 + (lane & 7)) * MSTRIDE
                                        + (lane >> 4) * 16);
    const int jb = ((lane >> 3) & 1) * 8 + (lane & 7);
    const int ub = 8 * wn + (lane >> 4);
    const int jsw = jb & 7;

    // mask expansion mapping: thread -> (row mi, j-quarter mq)
    const int mi = tid >> 2;        // 0..63
    const int mq = tid & 3;
    const uint32_t mst = mbuf + mi * MSTRIDE + mq * 16;

    const int r0 = 32 * wm + (lane >> 2);
    const int cb = 64 * wn + (lane & 3) * 2;
    float* gy = g_Wh + ((size_t)b * Nn + i0) * Fd;   // Y1 scratch (g_Wh is dead here)

    float dacc[2][8][4];

#pragma unroll 1
    for (int pass = 0; pass < 2; pass++) {
        const unsigned short* srcH =
            (pass == 0 ? g_X1h : g_X2h) + (size_t)b * Nn * Fd;
        const unsigned short* srcL =
            (pass == 0 ? g_X1l : g_X2l) + (size_t)b * Nn * Fd;
        const uint32_t* gM =
            (pass == 0 ? g_M1 : g_M2) + (size_t)(b * Nn + i0) * 64;

#pragma unroll
        for (int mt = 0; mt < 2; mt++)
#pragma unroll
            for (int n8 = 0; n8 < 8; n8++)
#pragma unroll
                for (int k = 0; k < 4; k++) dacc[mt][n8][k] = 0.f;

        // load packed masks for this pass (4096 words)
#pragma unroll
        for (int r = 0; r < 4; r++) {
            int idx = tid + r * 256;
            *(uint4*)&packed_s[idx * 4] = *(const uint4*)&gM[idx * 4];
        }

        // prologue: X chunk 0 -> slot 0
#pragma unroll
        for (int r = 0; r < 4; r++) {
            int e = tid + r * 256;
            int j = e >> 5, u = e & 31;
            uint32_t d = smem + j * 512 + ((u ^ (j & 7)) << 4);
            cp_async16(d, srcH + (size_t)j * Fd + u * 8);
            cp_async16(d + 16384, srcL + (size_t)j * Fd + u * 8);
        }
        cp_commit();

#pragma unroll 1
        for (int it = 0; it < NIT; it++) {
            __syncthreads();   // prior MMA done; packed_s/mbuf safe to touch

            // issue X(it+1) into the other slot
            if (it + 1 < NIT) {
                uint32_t dst = smem + ((it + 1) & 1) * SLOT_BYTES;
                size_t grow = (size_t)((it + 1) * KC) * Fd;
#pragma unroll
                for (int r = 0; r < 4; r++) {
                    int e = tid + r * 256;
                    int j = e >> 5, u = e & 31;
                    uint32_t d = dst + j * 512 + ((u ^ (j & 7)) << 4);
                    cp_async16(d, srcH + grow + (size_t)j * Fd + u * 8);
                    cp_async16(d + 16384, srcL + grow + (size_t)j * Fd + u * 8);
                }
            }
            cp_commit();

            // expand packed mask word -> bf16 tile (pure SMEM/ALU)
            {
                uint32_t bits = (packed_s[mi * 64 + it] >> (mq * 8)) & 0xFFu;
                uint32_t w[4] = {0, 0, 0, 0};
#pragma unroll
                for (int k = 0; k < 8; k++)
                    if ((bits >> k) & 1u) w[k >> 1] |= 0x3F80u << ((k & 1) * 16);
                asm volatile("st.shared.v4.b32 [%0], {%1,%2,%3,%4};"
                             :: "r"(mst), "r"(w[0]), "r"(w[1]), "r"(w[2]), "r"(w[3]) : "memory");
            }

            cp_wait1();        // X(it) landed
            __syncthreads();   // mask + X visible to all warps

            // MMA on chunk it
            const uint32_t xb = smem + (it & 1) * SLOT_BYTES;
#pragma unroll
            for (int ks = 0; ks < 2; ks++) {
                uint32_t a0[4], a1[4];
                ldsm4(a0, mbuf + aRowOff + ks * 32);
                ldsm4(a1, mbuf + aRowOff + 16 * MSTRIDE + ks * 32);
                const int j = jb + ks * 16;
                const uint32_t rowb = xb + j * 512;
#pragma unroll
                for (int ng = 0; ng < 4; ng++) {
                    const int u = ub + 2 * ng;
                    const uint32_t addrH = rowb + ((u ^ jsw) << 4);
                    uint32_t bh[4], bl[4];
                    ldsm4t(bh, addrH);
                    ldsm4t(bl, addrH + 16384);
                    mma16816(dacc[0][2 * ng],     a0, bh[0], bh[1]);
                    mma16816(dacc[0][2 * ng + 1], a0, bh[2], bh[3]);
                    mma16816(dacc[1][2 * ng],     a1, bh[0], bh[1]);
                    mma16816(dacc[1][2 * ng + 1], a1, bh[2], bh[3]);
                    mma16816(dacc[0][2 * ng],     a0, bl[0], bl[1]);
                    mma16816(dacc[0][2 * ng + 1], a0, bl[2], bl[3]);
                    mma16816(dacc[1][2 * ng],     a1, bl[0], bl[1]);
                    mma16816(dacc[1][2 * ng + 1], a1, bl[2], bl[3]);
                }
            }
        }

        if (pass == 0) {
            // stage e1p*Y1 to global scratch (per-thread private addresses)
#pragma unroll
            for (int mt = 0; mt < 2; mt++) {
                int ra = r0 + 16 * mt;
                float ea = e1p_s[ra], eb = e1p_s[ra + 8];
#pragma unroll
                for (int n8 = 0; n8 < 8; n8++) {
                    int c = cb + 8 * n8;
                    *(float2*)&gy[(size_t)ra * 256 + c] =
                        make_float2(ea * dacc[mt][n8][0], ea * dacc[mt][n8][1]);
                    *(float2*)&gy[(size_t)(ra + 8) * 256 + c] =
                        make_float2(eb * dacc[mt][n8][2], eb * dacc[mt][n8][3]);
                }
            }
        }
    }
    __syncthreads();   // main loop fully done; xs may overwrite slots/masks

    // combine: x = (gy + e1n*Y2) * invZ -> xs
#pragma unroll
    for (int mt = 0; mt < 2; mt++) {
        int ra = r0 + 16 * mt;
        float ea = e1n_s[ra], eb = e1n_s[ra + 8];
        float iza = invz_s[ra], izb = invz_s[ra + 8];
#pragma unroll
        for (int n8 = 0; n8 < 8; n8++) {
            int c = cb + 8 * n8;
            float2 ya = *(const float2*)&gy[(size_t)ra * 256 + c];
            float2 yb = *(const float2*)&gy[(size_t)(ra + 8) * 256 + c];
            xs[ra * XS_STRIDE + c]     = (ya.x + ea * dacc[mt][n8][0]) * iza;
            xs[ra * XS_STRIDE + c + 1] = (ya.y + ea * dacc[mt][n8][1]) * iza;
            xs[(ra + 8) * XS_STRIDE + c]     = (yb.x + eb * dacc[mt][n8][2]) * izb;
            xs[(ra + 8) * XS_STRIDE + c + 1] = (yb.y + eb * dacc[mt][n8][3]) * izb;
        }
    }
    __syncthreads();

    // LayerNorm stats: 4 threads per row
    {
        int row = tid >> 2, q = tid & 3;
        const float* xr = &xs[row * XS_STRIDE + q * 64];
        float sum = 0.f, ssq = 0.f;
#pragma unroll 8
        for (int k = 0; k < 64; k++) { float v = xr[k]; sum += v; ssq += v * v; }
        sum += __shfl_xor_sync(0xffffffffu, sum, 1);
        sum += __shfl_xor_sync(0xffffffffu, sum, 2);
        ssq += __shfl_xor_sync(0xffffffffu, ssq, 1);
        ssq += __shfl_xor_sync(0xffffffffu, ssq, 2);
        if (q == 0) {
            float mu = sum * (1.f / 256.f);
            float var = fmaxf(ssq * (1.f / 256.f) - mu * mu, 0.f);
            mu_s[row] = mu;
            rs_s[row] = rsqrtf(var + 1e-5f);
        }
    }
    __syncthreads();

    // gamma/beta + exact GELU, coalesced store (64 rows x 64 float4 = 4096)
    float* outb = out + ((size_t)b * Nn + i0) * Fd;
#pragma unroll 1
    for (int r = 0; r < 16; r++) {
        int u = tid + r * 256;
        int i = u >> 6;
        int c4 = (u & 63) * 4;
        float mu = mu_s[i], rs = rs_s[i];
        float4 xv = *(const float4*)&xs[i * XS_STRIDE + c4];
        float4 g = *(const float4*)&gamma[c4];
        float4 be = *(const float4*)&beta[c4];
        float x[4] = {xv.x, xv.y, xv.z, xv.w};
        float gv[4] = {g.x, g.y, g.z, g.w};
        float bv[4] = {be.x, be.y, be.z, be.w};
        float ov[4];
#pragma unroll
        for (int e = 0; e < 4; e++) {
            float y = (x[e] - mu) * rs * gv[e] + bv[e];
            ov[e] = 0.5f * y * (1.f + erff(y * 0.7071067811865475f));
        }
        *(float4*)&outb[(size_t)i * 256 + c4] = make_float4(ov[0], ov[1], ov[2], ov[3]);
    }
}

// ---------------------------------------------------------------------------
extern "C" void kernel_launch(void* const* d_in, const int* in_sizes, int n_in,
                              void* d_out, int out_size) {
    const float* h     = (const float*)d_in[0];
    const float* adj   = (const float*)d_in[1];
    const float* W     = (const float*)d_in[2];
    const float* a     = (const float*)d_in[3];
    const float* gamma = (const float*)d_in[4];
    const float* beta  = (const float*)d_in[5];
    float* out = (float*)d_out;

    cudaFuncSetAttribute(attn_mma_kernel,
                         cudaFuncAttributeMaxDynamicSharedMemorySize, DYN_B);

    gemm1_kernel<<<dim3(256, 4), 256>>>(h, W);
    score_kernel<<<2048, 256>>>(a);
    buildX_kernel<<<4096, 256>>>();
    mask_kernel<<<2048, 256>>>(adj);
    attn_mma_kernel<<<dim3(32, 8), 256, DYN_B>>>(gamma, beta, out);
}